// round 8
// baseline (speedup 1.0000x reference)
#include <cuda_runtime.h>
#include <cstdint>

// ---------------------------------------------------------------------------
// Problem constants
// ---------------------------------------------------------------------------
#define BB    4
#define CINC  256
#define COUTC 256
#define CMIDC 64
#define HH    64
#define WWD   64
#define HOUT  128
#define WOUT  128
#define NPIX  (BB*HH*WWD)      // 16384 base pixels per phase

// ---------------------------------------------------------------------------
// Scratch (no allocations allowed -> __device__ globals)
// ---------------------------------------------------------------------------
__device__ float g_xT [NPIX * CINC];        // input, NHWC:  [pix][ci]
__device__ float g_mid[NPIX * CMIDC];       // bottleneck,   [pix][cm]
__device__ float g_whT [9 * CINC  * COUTC]; // w_high  relayout [tap][ci][co]
__device__ float g_wl2T[9 * CMIDC * COUTC]; // w_low2  relayout [tap][cm][co]
__device__ float g_wl1T[CINC * CMIDC];      // w_low1  relayout [ci][cm]
__device__ int   g_list[8][NPIX];           // seg = branch*4 + phase
__device__ int   g_cnt[8];

// tap tables per phase (phase = py*2+px). dh/dw in {0,1}, kidx = kh*3+kw
__constant__ int c_dh[4][4] = {{0,0,0,0},{0,0,0,0},{1,0,0,0},{1,1,0,0}};
__constant__ int c_dw[4][4] = {{0,0,0,0},{1,0,0,0},{0,0,0,0},{1,0,1,0}};
__constant__ int c_kx[4][4] = {{4,0,0,0},{3,5,0,0},{1,7,0,0},{0,2,6,8}};

// ---------------------------------------------------------------------------
// Packed fp32x2 helpers (sm_103a FFMA2 path — full 128 MAC/cyc/SM)
// ---------------------------------------------------------------------------
__device__ __forceinline__ unsigned long long pk2(float x) {
    unsigned long long r;
    asm("mov.b64 %0, {%1, %1};" : "=l"(r) : "f"(x));
    return r;
}
__device__ __forceinline__ void fma2(unsigned long long &d,
                                     unsigned long long a,
                                     unsigned long long b) {
    asm("fma.rn.f32x2 %0, %1, %2, %0;" : "+l"(d) : "l"(a), "l"(b));
}
__device__ __forceinline__ float f_lo(unsigned long long v) {
    return __uint_as_float((unsigned)(v & 0xffffffffull));
}
__device__ __forceinline__ float f_hi(unsigned long long v) {
    return __uint_as_float((unsigned)(v >> 32));
}

// ---------------------------------------------------------------------------
// K0: zero segment counters
// ---------------------------------------------------------------------------
__global__ void k_zero() {
    if (threadIdx.x < 8) g_cnt[threadIdx.x] = 0;
}

// ---------------------------------------------------------------------------
// K1: input NCHW -> NHWC transpose (coalesced both sides via smem tile)
// ---------------------------------------------------------------------------
__global__ void k_tin(const float* __restrict__ x) {
    __shared__ float t[32][33];
    int b  = blockIdx.z;
    int p0 = blockIdx.x * 32;   // spatial (h*64+w)
    int c0 = blockIdx.y * 32;   // channel
    int tx = threadIdx.x, ty = threadIdx.y;
#pragma unroll
    for (int r = 0; r < 4; r++) {
        int c = c0 + ty + r * 8;
        t[ty + r * 8][tx] = x[((b * CINC + c) << 12) + p0 + tx];
    }
    __syncthreads();
#pragma unroll
    for (int r = 0; r < 4; r++) {
        int p = p0 + ty + r * 8;
        g_xT[((b << 12) + p) * CINC + c0 + tx] = t[tx][ty + r * 8];
    }
}

// ---------------------------------------------------------------------------
// K2: weight relayouts
//   w_high [ci][co][kh][kw] -> g_whT [kidx][ci][co]
//   w_low2 [cm][co][kh][kw] -> g_wl2T[kidx][cm][co]
//   w_low1 [cm][ci]         -> g_wl1T[ci][cm]
// ---------------------------------------------------------------------------
__global__ void k_tw(const float* __restrict__ wh,
                     const float* __restrict__ wl2,
                     const float* __restrict__ wl1) {
    int idx = blockIdx.x * blockDim.x + threadIdx.x;
    if (idx < 9 * CINC * COUTC) {
        int ci = idx / (COUTC * 9);
        int r  = idx % (COUTC * 9);
        int co = r / 9, t = r % 9;
        g_whT[(t * CINC + ci) * COUTC + co] = wh[idx];
    }
    if (idx < 9 * CMIDC * COUTC) {
        int cm = idx / (COUTC * 9);
        int r  = idx % (COUTC * 9);
        int co = r / 9, t = r % 9;
        g_wl2T[(t * CMIDC + cm) * COUTC + co] = wl2[idx];
    }
    if (idx < CMIDC * CINC) {
        int cm = idx / CINC, ci = idx % CINC;
        g_wl1T[ci * CMIDC + cm] = wl1[idx];
    }
}

// ---------------------------------------------------------------------------
// K3: bottleneck GEMM  mid[pix][cm] = xT[pix][:] @ wl1T[:, cm] + b_low1
//     M=16384, N=64, K=256; tile 128x64, 256 threads, 8x4 per thread
// ---------------------------------------------------------------------------
__global__ __launch_bounds__(256) void k_mid(const float* __restrict__ b_low1) {
    __shared__ float As[16][128];
    __shared__ float Bs[16][64];
    int tid = threadIdx.x;
    int m0  = blockIdx.x * 128;
    int tm = tid >> 4, tn = tid & 15;

    unsigned long long acc[8][2];
    {
        unsigned long long bi0 = *(const unsigned long long*)&b_low1[tn * 4];
        unsigned long long bi1 = *(const unsigned long long*)&b_low1[tn * 4 + 2];
#pragma unroll
        for (int i = 0; i < 8; i++) { acc[i][0] = bi0; acc[i][1] = bi1; }
    }

    float4 pa[2], pb;
    // prefetch chunk 0
    {
#pragma unroll
        for (int l = 0; l < 2; l++) {
            int idx = tid * 2 + l, row = idx >> 2, vc = idx & 3;
            pa[l] = *(const float4*)&g_xT[(m0 + row) * CINC + vc * 4];
        }
        int kr = tid >> 4, n = (tid & 15) * 4;
        pb = *(const float4*)&g_wl1T[kr * CMIDC + n];
    }

    for (int c = 0; c < 16; c++) {
        // regs -> smem
#pragma unroll
        for (int l = 0; l < 2; l++) {
            int idx = tid * 2 + l, row = idx >> 2, vc = idx & 3;
            As[vc * 4 + 0][row] = pa[l].x; As[vc * 4 + 1][row] = pa[l].y;
            As[vc * 4 + 2][row] = pa[l].z; As[vc * 4 + 3][row] = pa[l].w;
        }
        { int kr = tid >> 4, n = (tid & 15) * 4; *(float4*)&Bs[kr][n] = pb; }
        __syncthreads();
        // prefetch next
        if (c + 1 < 16) {
            int kt = (c + 1) * 16;
#pragma unroll
            for (int l = 0; l < 2; l++) {
                int idx = tid * 2 + l, row = idx >> 2, vc = idx & 3;
                pa[l] = *(const float4*)&g_xT[(m0 + row) * CINC + kt + vc * 4];
            }
            int kr = tid >> 4, n = (tid & 15) * 4;
            pb = *(const float4*)&g_wl1T[(kt + kr) * CMIDC + n];
        }
        // compute
#pragma unroll
        for (int k = 0; k < 16; k++) {
            float4 a0 = *(const float4*)&As[k][tm * 8];
            float4 a1 = *(const float4*)&As[k][tm * 8 + 4];
            ulonglong2 q = *(const ulonglong2*)&Bs[k][tn * 4];
            float av[8] = {a0.x, a0.y, a0.z, a0.w, a1.x, a1.y, a1.z, a1.w};
#pragma unroll
            for (int i = 0; i < 8; i++) {
                unsigned long long ap = pk2(av[i]);
                fma2(acc[i][0], ap, q.x);
                fma2(acc[i][1], ap, q.y);
            }
        }
        __syncthreads();
    }
#pragma unroll
    for (int i = 0; i < 8; i++) {
        int pix = m0 + tm * 8 + i;
        ulonglong2 v; v.x = acc[i][0]; v.y = acc[i][1];
        *(ulonglong2*)&g_mid[pix * CMIDC + tn * 4] = v;
    }
}

// ---------------------------------------------------------------------------
// K4: per-phase mask compaction (ordered within block, 1 atomic/block/branch)
// ---------------------------------------------------------------------------
__global__ void k_compact(const float* __restrict__ mask) {
    int phase = blockIdx.y, py = phase >> 1, px = phase & 1;
    int tid = threadIdx.x;
    int pid = blockIdx.x * 256 + tid;                 // (b<<12)|(h<<6)|w
    int b = pid >> 12, h = (pid >> 6) & 63, w = pid & 63;
    float mv = mask[(b * HOUT + 2 * h + py) * WOUT + 2 * w + px];
    bool hi = mv > 0.5f;

    __shared__ int cHi[8], oHi[8], oLo[8];
    __shared__ int bHi, bLo;
    int lane = tid & 31, wd = tid >> 5;
    unsigned bal = __ballot_sync(0xffffffffu, hi);
    if (lane == 0) cHi[wd] = __popc(bal);
    __syncthreads();
    if (tid == 0) {
        int sh = 0, sl = 0;
        for (int i = 0; i < 8; i++) {
            oHi[i] = sh; sh += cHi[i];
            oLo[i] = sl; sl += 32 - cHi[i];
        }
        bHi = atomicAdd(&g_cnt[phase], sh);
        bLo = atomicAdd(&g_cnt[4 + phase], sl);
    }
    __syncthreads();
    unsigned lt = (1u << lane) - 1u;
    if (hi) g_list[phase][bHi + oHi[wd] + __popc(bal & lt)] = pid;
    else    g_list[4 + phase][bLo + oLo[wd] + __popc((~bal) & lt)] = pid;
}

// ---------------------------------------------------------------------------
// K5: main list-gathered implicit GEMM.
//   seg = branch*4+phase. branch 0: A=g_xT (K=256/tap), W=g_whT, bias=b_high
//                         branch 1: A=g_mid (K=64/tap),  W=g_wl2T, bias=b_low2
//   Tile 128(pixels) x 128(co), KC=16, double-buffered smem, 8x8/thread (f32x2)
// ---------------------------------------------------------------------------
__global__ __launch_bounds__(256, 2) void k_main(const float* __restrict__ b_high,
                                                 const float* __restrict__ b_low2,
                                                 float* __restrict__ out) {
    int seg   = blockIdx.z;
    int count = g_cnt[seg];
    int m0    = blockIdx.x * 128;
    if (m0 >= count) return;

    int branch = seg >> 2, phase = seg & 3;
    int py = phase >> 1, px = phase & 1;
    int Kin  = branch ? CMIDC : CINC;
    int ntap = (py + 1) * (px + 1);
    int Ktot = ntap * Kin;
    const float* Ab   = branch ? g_mid  : g_xT;
    const float* Wb   = branch ? g_wl2T : g_whT;
    const float* bias = branch ? b_low2 : b_high;
    int co0 = blockIdx.y * 128;

    __shared__ float As[2][16][128];
    __shared__ float Bs[2][16][128];
    __shared__ int   sid[128];

    int tid = threadIdx.x;
    if (tid < 128) {
        int m = m0 + tid;
        sid[tid] = g_list[seg][m < count ? m : count - 1];
    }
    int tm = tid >> 4, tn = tid & 15;

    unsigned long long acc[8][4];
    {
        const unsigned long long* bp =
            (const unsigned long long*)&bias[co0 + tn * 8];
#pragma unroll
        for (int jj = 0; jj < 4; jj++) {
            unsigned long long v = bp[jj];
#pragma unroll
            for (int i = 0; i < 8; i++) acc[i][jj] = v;
        }
    }
    __syncthreads();

    float4 pa[2], pb[2];
    auto loadG = [&](int kt) {
        int tap = kt / Kin;
        int ci0 = kt - tap * Kin;
        int dh = c_dh[phase][tap], dw = c_dw[phase][tap], kx = c_kx[phase][tap];
#pragma unroll
        for (int l = 0; l < 2; l++) {
            int idx = tid * 2 + l, row = idx >> 2, vc = idx & 3;
            int id = sid[row];
            int b = id >> 12, h = (id >> 6) & 63, w = id & 63;
            int hh = h + dh, ww = w + dw;
            if (hh < HH && ww < WWD)
                pa[l] = *(const float4*)&Ab[(((b << 6) + hh) * 64 + ww) * Kin + ci0 + vc * 4];
            else
                pa[l] = make_float4(0.f, 0.f, 0.f, 0.f);
        }
#pragma unroll
        for (int l = 0; l < 2; l++) {
            int idx = tid * 2 + l, kr = idx >> 5, c4 = idx & 31;
            pb[l] = *(const float4*)&Wb[(kx * Kin + ci0 + kr) * COUTC + co0 + c4 * 4];
        }
    };
    auto storeS = [&](int bf) {
#pragma unroll
        for (int l = 0; l < 2; l++) {
            int idx = tid * 2 + l, row = idx >> 2, vc = idx & 3;
            As[bf][vc * 4 + 0][row] = pa[l].x;
            As[bf][vc * 4 + 1][row] = pa[l].y;
            As[bf][vc * 4 + 2][row] = pa[l].z;
            As[bf][vc * 4 + 3][row] = pa[l].w;
            int kr = idx >> 5, c4 = idx & 31;
            *(float4*)&Bs[bf][kr][c4 * 4] = pb[l];
        }
    };

    loadG(0);
    storeS(0);
    __syncthreads();

    int nCh = Ktot >> 4;
    int bf = 0;
    for (int c = 0; c < nCh; c++) {
        if (c + 1 < nCh) loadG((c + 1) << 4);
#pragma unroll
        for (int k = 0; k < 16; k++) {
            float4 a0 = *(const float4*)&As[bf][k][tm * 8];
            float4 a1 = *(const float4*)&As[bf][k][tm * 8 + 4];
            ulonglong2 q0 = *(const ulonglong2*)&Bs[bf][k][tn * 8];
            ulonglong2 q1 = *(const ulonglong2*)&Bs[bf][k][tn * 8 + 4];
            float av[8] = {a0.x, a0.y, a0.z, a0.w, a1.x, a1.y, a1.z, a1.w};
#pragma unroll
            for (int i = 0; i < 8; i++) {
                unsigned long long ap = pk2(av[i]);
                fma2(acc[i][0], ap, q0.x);
                fma2(acc[i][1], ap, q0.y);
                fma2(acc[i][2], ap, q1.x);
                fma2(acc[i][3], ap, q1.y);
            }
        }
        if (c + 1 < nCh) storeS(bf ^ 1);
        __syncthreads();
        bf ^= 1;
    }

    // scatter store to NCHW output (partial sectors merge in L2; out fits L2)
#pragma unroll
    for (int i = 0; i < 8; i++) {
        int m = m0 + tm * 8 + i;
        if (m >= count) continue;
        int id = sid[tm * 8 + i];
        int b = id >> 12, h = (id >> 6) & 63, w = id & 63;
        int ho = 2 * h + py, wo = 2 * w + px;
        float* op = out + (((size_t)b * COUTC + co0 + tn * 8) * HOUT + ho) * WOUT + wo;
#pragma unroll
        for (int jj = 0; jj < 4; jj++) {
            unsigned long long v = acc[i][jj];
            op[(size_t)(2 * jj) * (HOUT * WOUT)]     = f_lo(v);
            op[(size_t)(2 * jj + 1) * (HOUT * WOUT)] = f_hi(v);
        }
    }
}

// ---------------------------------------------------------------------------
// launch
// Inputs (metadata order): inx, mask, inv_mask, w_high, b_high,
//                          w_low1, b_low1, w_low2, b_low2
// ---------------------------------------------------------------------------
extern "C" void kernel_launch(void* const* d_in, const int* in_sizes, int n_in,
                              void* d_out, int out_size) {
    const float* inx    = (const float*)d_in[0];
    const float* mask   = (const float*)d_in[1];
    /* inv_mask d_in[2] unused: mask is binary, selection is exact */
    const float* w_high = (const float*)d_in[3];
    const float* b_high = (const float*)d_in[4];
    const float* w_low1 = (const float*)d_in[5];
    const float* b_low1 = (const float*)d_in[6];
    const float* w_low2 = (const float*)d_in[7];
    const float* b_low2 = (const float*)d_in[8];
    float* out = (float*)d_out;

    k_zero<<<1, 32>>>();
    k_tin<<<dim3(128, 8, BB), dim3(32, 8)>>>(inx);
    k_tw<<<(9 * CINC * COUTC + 255) / 256, 256>>>(w_high, w_low2, w_low1);
    k_mid<<<NPIX / 128, 256>>>(b_low1);
    k_compact<<<dim3(NPIX / 256, 4), 256>>>(mask);
    k_main<<<dim3(NPIX / 128, COUTC / 128, 8), 256>>>(b_high, b_low2, out);
}

// round 12
// speedup vs baseline: 1.6200x; 1.6200x over previous
#include <cuda_runtime.h>
#include <cuda_bf16.h>
#include <cstdint>

// ---------------------------------------------------------------------------
// Problem constants
// ---------------------------------------------------------------------------
#define BB    4
#define CINC  256
#define COUTC 256
#define CMIDC 64
#define HH    64
#define WWD   64
#define HOUT  128
#define WOUT  128
#define NPIX  16384
#define K3H   768     // 3 * CINC  (packed K: [aH|aH|aL])
#define K3L   192     // 3 * CMIDC

// ---------------------------------------------------------------------------
// Scratch (__device__ globals; no allocations allowed)
// ---------------------------------------------------------------------------
__device__ __nv_bfloat16 g_xP  [NPIX * K3H];      // input packed  [pix][768]
__device__ __nv_bfloat16 g_midP[NPIX * K3L];      // mid packed    [pix][192]
__device__ __nv_bfloat16 g_whP [9 * COUTC * K3H]; // [tap][co][768] = [bH|bL|bH]
__device__ __nv_bfloat16 g_wl2P[9 * COUTC * K3L]; // [tap][co][192]
__device__ __nv_bfloat16 g_w1P [CMIDC * K3H];     // [cm][768]
__device__ int           g_list[8][NPIX];         // seg = branch*4 + phase
__device__ int           g_cnt[8];

// tap tables per phase (phase = py*2+px). dh/dw in {0,1}, kidx = kh*3+kw
__constant__ int c_dh[4][4] = {{0,0,0,0},{0,0,0,0},{1,0,0,0},{1,1,0,0}};
__constant__ int c_dw[4][4] = {{0,0,0,0},{1,0,0,0},{0,0,0,0},{1,0,1,0}};
__constant__ int c_kx[4][4] = {{4,0,0,0},{3,5,0,0},{1,7,0,0},{0,2,6,8}};

// ---------------------------------------------------------------------------
// Helpers
// ---------------------------------------------------------------------------
__device__ __forceinline__ void bsplit(float v, __nv_bfloat16 &h, __nv_bfloat16 &l) {
    h = __float2bfloat16(v);
    l = __float2bfloat16(v - __bfloat162float(h));
}
__device__ __forceinline__ uint32_t smem_u32(const void* p) {
    uint32_t a;
    asm("{ .reg .u64 t; cvta.to.shared.u64 t, %1; cvt.u32.u64 %0, t; }"
        : "=r"(a) : "l"(p));
    return a;
}
__device__ __forceinline__ void ldsm4(uint32_t &r0, uint32_t &r1,
                                      uint32_t &r2, uint32_t &r3, uint32_t a) {
    asm volatile("ldmatrix.sync.aligned.m8n8.x4.shared.b16 {%0,%1,%2,%3}, [%4];"
                 : "=r"(r0), "=r"(r1), "=r"(r2), "=r"(r3) : "r"(a));
}
__device__ __forceinline__ void mma_bf16(float* c, const uint32_t* a,
                                         const uint32_t* b) {
    asm volatile(
        "mma.sync.aligned.m16n8k16.row.col.f32.bf16.bf16.f32 "
        "{%0,%1,%2,%3}, {%4,%5,%6,%7}, {%8,%9}, {%0,%1,%2,%3};"
        : "+f"(c[0]), "+f"(c[1]), "+f"(c[2]), "+f"(c[3])
        : "r"(a[0]), "r"(a[1]), "r"(a[2]), "r"(a[3]), "r"(b[0]), "r"(b[1]));
}
__device__ __forceinline__ void cpa16(uint32_t dst, const void* src, int sz) {
    asm volatile("cp.async.cg.shared.global [%0], [%1], 16, %2;"
                 :: "r"(dst), "l"(src), "r"(sz) : "memory");
}
__device__ __forceinline__ void cpa_commit() {
    asm volatile("cp.async.commit_group;" ::: "memory");
}

// ---------------------------------------------------------------------------
// K0: zero segment counters
// ---------------------------------------------------------------------------
__global__ void k_zero() {
    if (threadIdx.x < 8) g_cnt[threadIdx.x] = 0;
}

// ---------------------------------------------------------------------------
// K1: input NCHW -> packed NHWC bf16 [aH|aH|aL]
// ---------------------------------------------------------------------------
__global__ void k_tin(const float* __restrict__ x) {
    __shared__ float t[32][33];
    int b  = blockIdx.z;
    int p0 = blockIdx.x * 32;
    int c0 = blockIdx.y * 32;
    int tx = threadIdx.x, ty = threadIdx.y;
#pragma unroll
    for (int r = 0; r < 4; r++) {
        int c = c0 + ty + r * 8;
        t[ty + r * 8][tx] = x[((b * CINC + c) << 12) + p0 + tx];
    }
    __syncthreads();
#pragma unroll
    for (int r = 0; r < 4; r++) {
        int p = p0 + ty + r * 8;
        float v = t[tx][ty + r * 8];
        __nv_bfloat16 h, l; bsplit(v, h, l);
        int o = ((b << 12) + p) * K3H + c0 + tx;
        g_xP[o]       = h;
        g_xP[o + 256] = h;
        g_xP[o + 512] = l;
    }
}

// ---------------------------------------------------------------------------
// K2: weight relayout + split + pack [bH|bL|bH]
// ---------------------------------------------------------------------------
__global__ void k_tw(const float* __restrict__ wh,
                     const float* __restrict__ wl2,
                     const float* __restrict__ wl1) {
    int idx = blockIdx.x * blockDim.x + threadIdx.x;
    if (idx < 9 * CINC * COUTC) {
        int ci = idx / (COUTC * 9);
        int r  = idx % (COUTC * 9);
        int co = r / 9, t = r % 9;
        __nv_bfloat16 h, l; bsplit(wh[idx], h, l);
        int base = (t * COUTC + co) * K3H;
        g_whP[base + ci]       = h;
        g_whP[base + 256 + ci] = l;
        g_whP[base + 512 + ci] = h;
    }
    if (idx < 9 * CMIDC * COUTC) {
        int cm = idx / (COUTC * 9);
        int r  = idx % (COUTC * 9);
        int co = r / 9, t = r % 9;
        __nv_bfloat16 h, l; bsplit(wl2[idx], h, l);
        int base = (t * COUTC + co) * K3L;
        g_wl2P[base + cm]       = h;
        g_wl2P[base + 64 + cm]  = l;
        g_wl2P[base + 128 + cm] = h;
    }
    if (idx < CMIDC * CINC) {
        int cm = idx / CINC, ci = idx % CINC;
        __nv_bfloat16 h, l; bsplit(wl1[idx], h, l);
        int base = cm * K3H;
        g_w1P[base + ci]       = h;
        g_w1P[base + 256 + ci] = l;
        g_w1P[base + 512 + ci] = h;
    }
}

// ---------------------------------------------------------------------------
// K3: bottleneck GEMM via HMMA.  mid = xP @ w1P^T + b_low1, K_eff=768, N=64.
//     CTA 128x64, 8 warps of 32x32. Output: packed bf16 [mH|mH|mL].
// ---------------------------------------------------------------------------
#define MID_A0   0
#define MID_A1   16384
#define MID_B0   32768
#define MID_B1   40960
#define MID_BIAS 49152
#define MID_SMEM 49408

__global__ __launch_bounds__(256, 2)
void k_mid(const float* __restrict__ b_low1) {
    extern __shared__ char sm[];
    int tid = threadIdx.x;
    int m0  = blockIdx.x * 128;
    uint32_t sb = smem_u32(sm);
    float* sbias = (float*)(sm + MID_BIAS);
    if (tid < 64) sbias[tid] = b_low1[tid];

    int wid = tid >> 5, lane = tid & 31;
    int wm = wid & 3, wn = wid >> 2;
    float acc[2][4][4];
#pragma unroll
    for (int i = 0; i < 2; i++)
#pragma unroll
        for (int j = 0; j < 4; j++)
#pragma unroll
            for (int k = 0; k < 4; k++) acc[i][j][k] = 0.f;

    int arow = tid >> 1, aj0 = (tid & 1) * 4;
    int brow = tid >> 2, bj0 = (tid & 3) * 2;

    auto stage = [&](int c, int buf) {
        int koff = c * 64;
        const char* asrc = (const char*)(g_xP + (size_t)(m0 + arow) * K3H + koff);
        uint32_t ab = sb + (buf ? MID_A1 : MID_A0) + arow * 128;
        const char* bsrc = (const char*)(g_w1P + (size_t)brow * K3H + koff);
        uint32_t bb = sb + (buf ? MID_B1 : MID_B0) + brow * 128;
#pragma unroll
        for (int i = 0; i < 4; i++) {
            int j16 = aj0 + i;
            cpa16(ab + ((j16 ^ (arow & 7)) * 16), asrc + j16 * 16, 16);
        }
#pragma unroll
        for (int i = 0; i < 2; i++) {
            int j16 = bj0 + i;
            cpa16(bb + ((j16 ^ (brow & 7)) * 16), bsrc + j16 * 16, 16);
        }
        cpa_commit();
    };

    stage(0, 0);
    const int nCh = 12;
    for (int c = 0; c < nCh; c++) {
        int buf = c & 1;
        if (c + 1 < nCh) {
            stage(c + 1, buf ^ 1);
            asm volatile("cp.async.wait_group 1;" ::: "memory");
        } else {
            asm volatile("cp.async.wait_group 0;" ::: "memory");
        }
        __syncthreads();
        uint32_t aB = sb + (buf ? MID_A1 : MID_A0);
        uint32_t bB = sb + (buf ? MID_B1 : MID_B0);
#pragma unroll
        for (int ks = 0; ks < 4; ks++) {
            int k0 = ks * 16;
            uint32_t a[2][4], bt[4][2];
#pragma unroll
            for (int mi = 0; mi < 2; mi++) {
                int row = wm * 32 + mi * 16 + (lane & 15);
                int j16 = (k0 >> 3) + (lane >> 4);
                uint32_t addr = aB + row * 128 + ((j16 ^ (row & 7)) * 16);
                ldsm4(a[mi][0], a[mi][1], a[mi][2], a[mi][3], addr);
            }
#pragma unroll
            for (int g = 0; g < 2; g++) {
                int row = wn * 32 + g * 16 + (lane & 15);
                int j16 = (k0 >> 3) + (lane >> 4);
                uint32_t addr = bB + row * 128 + ((j16 ^ (row & 7)) * 16);
                uint32_t r0, r1, r2, r3;
                ldsm4(r0, r1, r2, r3, addr);
                bt[2 * g][0] = r0;     bt[2 * g][1] = r2;
                bt[2 * g + 1][0] = r1; bt[2 * g + 1][1] = r3;
            }
#pragma unroll
            for (int mi = 0; mi < 2; mi++)
#pragma unroll
                for (int ni = 0; ni < 4; ni++)
                    mma_bf16(acc[mi][ni], a[mi], bt[ni]);
        }
        __syncthreads();
    }

    // epilogue: + bias, split, pack [mH|mH|mL]
#pragma unroll
    for (int mi = 0; mi < 2; mi++)
#pragma unroll
        for (int hb = 0; hb < 2; hb++) {
            int rloc = wm * 32 + mi * 16 + hb * 8 + (lane >> 2);
            int pix = m0 + rloc;
            __nv_bfloat16* mp = g_midP + (size_t)pix * K3L;
#pragma unroll
            for (int ni = 0; ni < 4; ni++) {
#pragma unroll
                for (int e = 0; e < 2; e++) {
                    int cm = wn * 32 + ni * 8 + (lane & 3) * 2 + e;
                    float v = acc[mi][ni][hb * 2 + e] + sbias[cm];
                    __nv_bfloat16 h, l; bsplit(v, h, l);
                    mp[cm] = h; mp[64 + cm] = h; mp[128 + cm] = l;
                }
            }
        }
}

// ---------------------------------------------------------------------------
// K4: per-phase mask compaction
// ---------------------------------------------------------------------------
__global__ void k_compact(const float* __restrict__ mask) {
    int phase = blockIdx.y, py = phase >> 1, px = phase & 1;
    int tid = threadIdx.x;
    int pid = blockIdx.x * 256 + tid;
    int b = pid >> 12, h = (pid >> 6) & 63, w = pid & 63;
    float mv = mask[(b * HOUT + 2 * h + py) * WOUT + 2 * w + px];
    bool hi = mv > 0.5f;

    __shared__ int cHi[8], oHi[8], oLo[8];
    __shared__ int bHi, bLo;
    int lane = tid & 31, wd = tid >> 5;
    unsigned bal = __ballot_sync(0xffffffffu, hi);
    if (lane == 0) cHi[wd] = __popc(bal);
    __syncthreads();
    if (tid == 0) {
        int sh = 0, sl = 0;
        for (int i = 0; i < 8; i++) {
            oHi[i] = sh; sh += cHi[i];
            oLo[i] = sl; sl += 32 - cHi[i];
        }
        bHi = atomicAdd(&g_cnt[phase], sh);
        bLo = atomicAdd(&g_cnt[4 + phase], sl);
    }
    __syncthreads();
    unsigned lt = (1u << lane) - 1u;
    if (hi) g_list[phase][bHi + oHi[wd] + __popc(bal & lt)] = pid;
    else    g_list[4 + phase][bLo + oLo[wd] + __popc((~bal) & lt)] = pid;
}

// ---------------------------------------------------------------------------
// K5: main list-gathered implicit GEMM via HMMA bf16 (3-term split in K).
//     CTA 128 px x 128 co, 8 warps of 32x64, K chunks of 64, cp.async double buf
// ---------------------------------------------------------------------------
#define KM_A0   0
#define KM_A1   16384
#define KM_B0   32768
#define KM_B1   49152
#define KM_SID  65536
#define KM_BIAS 66048
#define KM_SMEM 66560

__global__ __launch_bounds__(256, 2)
void k_main(const float* __restrict__ b_high, const float* __restrict__ b_low2,
            float* __restrict__ out) {
    extern __shared__ char sm[];
    int seg   = blockIdx.z;
    int count = g_cnt[seg];
    int m0    = blockIdx.x * 128;
    if (m0 >= count) return;

    int branch = seg >> 2, phase = seg & 3;
    int py = phase >> 1, px = phase & 1;
    int KROW = branch ? K3L : K3H;
    int cpt  = KROW >> 6;           // chunks per tap: 12 high / 3 low
    int ntap = (py + 1) * (px + 1);
    int nCh  = ntap * cpt;
    const __nv_bfloat16* Ab = branch ? g_midP : g_xP;
    const __nv_bfloat16* Wb = branch ? g_wl2P : g_whP;
    const float* bias = branch ? b_low2 : b_high;
    int co0 = blockIdx.y * 128;

    int* sid = (int*)(sm + KM_SID);
    float* sbias = (float*)(sm + KM_BIAS);
    int tid = threadIdx.x;
    if (tid < 128) {
        int m = m0 + tid;
        sid[tid]   = g_list[seg][m < count ? m : count - 1];
        sbias[tid] = bias[co0 + tid];
    }
    __syncthreads();
    uint32_t sb = smem_u32(sm);

    int wid = tid >> 5, lane = tid & 31;
    int wm = wid & 3, wn = wid >> 2;
    float acc[2][8][4];
#pragma unroll
    for (int i = 0; i < 2; i++)
#pragma unroll
        for (int j = 0; j < 8; j++)
#pragma unroll
            for (int k = 0; k < 4; k++) acc[i][j][k] = 0.f;

    int srow = tid >> 1, sj0 = (tid & 1) * 4;

    auto stage = [&](int c, int buf) {
        int tap  = c / cpt;
        int koff = (c - tap * cpt) << 6;   // element offset within K row
        int dh = c_dh[phase][tap], dw = c_dw[phase][tap], kx = c_kx[phase][tap];
        int id = sid[srow];
        int b = id >> 12, h = (id >> 6) & 63, w = id & 63;
        int hh = h + dh, ww = w + dw;
        bool ok = (hh < HH) && (ww < WWD);
        const char* asrc = (const char*)(Ab +
            (size_t)((((b << 6) + (ok ? hh : h)) << 6) + (ok ? ww : w)) * KROW + koff);
        uint32_t ab = sb + (buf ? KM_A1 : KM_A0) + srow * 128;
        const char* bsrc = (const char*)(Wb +
            (size_t)(kx * COUTC + co0 + srow) * KROW + koff);
        uint32_t bb = sb + (buf ? KM_B1 : KM_B0) + srow * 128;
        int asz = ok ? 16 : 0;
#pragma unroll
        for (int i = 0; i < 4; i++) {
            int j16 = sj0 + i;
            uint32_t sw = (uint32_t)((j16 ^ (srow & 7)) * 16);
            cpa16(ab + sw, asrc + j16 * 16, asz);
            cpa16(bb + sw, bsrc + j16 * 16, 16);
        }
        cpa_commit();
    };

    stage(0, 0);
    for (int c = 0; c < nCh; c++) {
        int buf = c & 1;
        if (c + 1 < nCh) {
            stage(c + 1, buf ^ 1);
            asm volatile("cp.async.wait_group 1;" ::: "memory");
        } else {
            asm volatile("cp.async.wait_group 0;" ::: "memory");
        }
        __syncthreads();
        uint32_t aB = sb + (buf ? KM_A1 : KM_A0);
        uint32_t bB = sb + (buf ? KM_B1 : KM_B0);
#pragma unroll
        for (int ks = 0; ks < 4; ks++) {
            int k0 = ks * 16;
            uint32_t a[2][4], bt[8][2];
#pragma unroll
            for (int mi = 0; mi < 2; mi++) {
                int row = wm * 32 + mi * 16 + (lane & 15);
                int j16 = (k0 >> 3) + (lane >> 4);
                uint32_t addr = aB + row * 128 + ((j16 ^ (row & 7)) * 16);
                ldsm4(a[mi][0], a[mi][1], a[mi][2], a[mi][3], addr);
            }
#pragma unroll
            for (int g = 0; g < 4; g++) {
                int row = wn * 64 + g * 16 + (lane & 15);
                int j16 = (k0 >> 3) + (lane >> 4);
                uint32_t addr = bB + row * 128 + ((j16 ^ (row & 7)) * 16);
                uint32_t r0, r1, r2, r3;
                ldsm4(r0, r1, r2, r3, addr);
                bt[2 * g][0] = r0;     bt[2 * g][1] = r2;
                bt[2 * g + 1][0] = r1; bt[2 * g + 1][1] = r3;
            }
#pragma unroll
            for (int mi = 0; mi < 2; mi++)
#pragma unroll
                for (int ni = 0; ni < 8; ni++)
                    mma_bf16(acc[mi][ni], a[mi], bt[ni]);
        }
        __syncthreads();
    }

    // epilogue: + bias, scatter to NCHW
#pragma unroll
    for (int mi = 0; mi < 2; mi++)
#pragma unroll
        for (int hb = 0; hb < 2; hb++) {
            int rloc = wm * 32 + mi * 16 + hb * 8 + (lane >> 2);
            if (m0 + rloc >= count) continue;
            int id = sid[rloc];
            int b = id >> 12, h = (id >> 6) & 63, w = id & 63;
            int ho = 2 * h + py, wo = 2 * w + px;
            float* op = out + (((size_t)b * COUTC + co0) * HOUT + ho) * WOUT + wo;
#pragma unroll
            for (int ni = 0; ni < 8; ni++) {
                int n0 = wn * 64 + ni * 8 + (lane & 3) * 2;
                op[(size_t)n0 * (HOUT * WOUT)] =
                    acc[mi][ni][hb * 2 + 0] + sbias[n0];
                op[(size_t)(n0 + 1) * (HOUT * WOUT)] =
                    acc[mi][ni][hb * 2 + 1] + sbias[n0 + 1];
            }
        }
}

// ---------------------------------------------------------------------------
// launch
// Inputs (metadata order): inx, mask, inv_mask, w_high, b_high,
//                          w_low1, b_low1, w_low2, b_low2
// ---------------------------------------------------------------------------
extern "C" void kernel_launch(void* const* d_in, const int* in_sizes, int n_in,
                              void* d_out, int out_size) {
    const float* inx    = (const float*)d_in[0];
    const float* mask   = (const float*)d_in[1];
    const float* w_high = (const float*)d_in[3];
    const float* b_high = (const float*)d_in[4];
    const float* w_low1 = (const float*)d_in[5];
    const float* b_low1 = (const float*)d_in[6];
    const float* w_low2 = (const float*)d_in[7];
    const float* b_low2 = (const float*)d_in[8];
    float* out = (float*)d_out;

    cudaFuncSetAttribute(k_mid,  cudaFuncAttributeMaxDynamicSharedMemorySize,
                         MID_SMEM);
    cudaFuncSetAttribute(k_main, cudaFuncAttributeMaxDynamicSharedMemorySize,
                         KM_SMEM);

    k_zero<<<1, 32>>>();
    k_tin<<<dim3(128, 8, BB), dim3(32, 8)>>>(inx);
    k_tw<<<(9 * CINC * COUTC + 255) / 256, 256>>>(w_high, w_low2, w_low1);
    k_mid<<<NPIX / 128, 256, MID_SMEM>>>(b_low1);
    k_compact<<<dim3(NPIX / 256, 4), 256>>>(mask);
    k_main<<<dim3(NPIX / 128, 2, 8), 256, KM_SMEM>>>(b_high, b_low2, out);
}

// round 13
// speedup vs baseline: 2.0410x; 1.2599x over previous
#include <cuda_runtime.h>
#include <cuda_bf16.h>
#include <cstdint>

// ---------------------------------------------------------------------------
// Problem constants
// ---------------------------------------------------------------------------
#define BB    4
#define CINC  256
#define COUTC 256
#define CMIDC 64
#define HH    64
#define WWD   64
#define HOUT  128
#define WOUT  128
#define NPIX  16384

// ---------------------------------------------------------------------------
// Scratch (__device__ globals; no allocations allowed)
// ---------------------------------------------------------------------------
__device__ __nv_bfloat16 g_xH [NPIX * CINC];       // input hi  [pix][ci]
__device__ __nv_bfloat16 g_xL [NPIX * CINC];       // input lo
__device__ __nv_bfloat16 g_mH [NPIX * CMIDC];      // mid hi    [pix][cm]
__device__ __nv_bfloat16 g_mL [NPIX * CMIDC];      // mid lo
__device__ __nv_bfloat16 g_whH [9 * COUTC * CINC]; // [tap][co][ci]
__device__ __nv_bfloat16 g_whL [9 * COUTC * CINC];
__device__ __nv_bfloat16 g_wl2H[9 * COUTC * CMIDC];
__device__ __nv_bfloat16 g_wl2L[9 * COUTC * CMIDC];
__device__ __nv_bfloat16 g_w1H [CMIDC * CINC];     // [cm][ci] (native layout)
__device__ __nv_bfloat16 g_w1L [CMIDC * CINC];
__device__ int           g_list[8][NPIX];          // seg = branch*4 + phase
__device__ int           g_cnt[8];

// tap tables per phase (phase = py*2+px). dh/dw in {0,1}, kidx = kh*3+kw
__constant__ int c_dh[4][4] = {{0,0,0,0},{0,0,0,0},{1,0,0,0},{1,1,0,0}};
__constant__ int c_dw[4][4] = {{0,0,0,0},{1,0,0,0},{0,0,0,0},{1,0,1,0}};
__constant__ int c_kx[4][4] = {{4,0,0,0},{3,5,0,0},{1,7,0,0},{0,2,6,8}};

// ---------------------------------------------------------------------------
// Helpers
// ---------------------------------------------------------------------------
__device__ __forceinline__ void bsplit(float v, __nv_bfloat16 &h, __nv_bfloat16 &l) {
    h = __float2bfloat16(v);
    l = __float2bfloat16(v - __bfloat162float(h));
}
__device__ __forceinline__ uint32_t smem_u32(const void* p) {
    uint32_t a;
    asm("{ .reg .u64 t; cvta.to.shared.u64 t, %1; cvt.u32.u64 %0, t; }"
        : "=r"(a) : "l"(p));
    return a;
}
__device__ __forceinline__ void ldsm4(uint32_t &r0, uint32_t &r1,
                                      uint32_t &r2, uint32_t &r3, uint32_t a) {
    asm volatile("ldmatrix.sync.aligned.m8n8.x4.shared.b16 {%0,%1,%2,%3}, [%4];"
                 : "=r"(r0), "=r"(r1), "=r"(r2), "=r"(r3) : "r"(a));
}
__device__ __forceinline__ void mma_bf16(float* c, const uint32_t* a,
                                         const uint32_t* b) {
    asm volatile(
        "mma.sync.aligned.m16n8k16.row.col.f32.bf16.bf16.f32 "
        "{%0,%1,%2,%3}, {%4,%5,%6,%7}, {%8,%9}, {%0,%1,%2,%3};"
        : "+f"(c[0]), "+f"(c[1]), "+f"(c[2]), "+f"(c[3])
        : "r"(a[0]), "r"(a[1]), "r"(a[2]), "r"(a[3]), "r"(b[0]), "r"(b[1]));
}
__device__ __forceinline__ void cpa16(uint32_t dst, const void* src, int sz) {
    asm volatile("cp.async.cg.shared.global [%0], [%1], 16, %2;"
                 :: "r"(dst), "l"(src), "r"(sz) : "memory");
}
__device__ __forceinline__ void cpa_commit() {
    asm volatile("cp.async.commit_group;" ::: "memory");
}

// ---------------------------------------------------------------------------
// K0: zero segment counters
// ---------------------------------------------------------------------------
__global__ void k_zero() {
    if (threadIdx.x < 8) g_cnt[threadIdx.x] = 0;
}

// ---------------------------------------------------------------------------
// K1: input NCHW -> NHWC bf16 hi/lo split
// ---------------------------------------------------------------------------
__global__ void k_tin(const float* __restrict__ x) {
    __shared__ float t[32][33];
    int b  = blockIdx.z;
    int p0 = blockIdx.x * 32;
    int c0 = blockIdx.y * 32;
    int tx = threadIdx.x, ty = threadIdx.y;
#pragma unroll
    for (int r = 0; r < 4; r++) {
        int c = c0 + ty + r * 8;
        t[ty + r * 8][tx] = x[((b * CINC + c) << 12) + p0 + tx];
    }
    __syncthreads();
#pragma unroll
    for (int r = 0; r < 4; r++) {
        int p = p0 + ty + r * 8;
        float v = t[tx][ty + r * 8];
        __nv_bfloat16 h, l; bsplit(v, h, l);
        int o = ((b << 12) + p) * CINC + c0 + tx;
        g_xH[o] = h;
        g_xL[o] = l;
    }
}

// ---------------------------------------------------------------------------
// K2: weight relayout + hi/lo split
// ---------------------------------------------------------------------------
__global__ void k_tw(const float* __restrict__ wh,
                     const float* __restrict__ wl2,
                     const float* __restrict__ wl1) {
    int idx = blockIdx.x * blockDim.x + threadIdx.x;
    if (idx < 9 * CINC * COUTC) {
        int ci = idx / (COUTC * 9);
        int r  = idx % (COUTC * 9);
        int co = r / 9, t = r % 9;
        __nv_bfloat16 h, l; bsplit(wh[idx], h, l);
        int o = (t * COUTC + co) * CINC + ci;
        g_whH[o] = h; g_whL[o] = l;
    }
    if (idx < 9 * CMIDC * COUTC) {
        int cm = idx / (COUTC * 9);
        int r  = idx % (COUTC * 9);
        int co = r / 9, t = r % 9;
        __nv_bfloat16 h, l; bsplit(wl2[idx], h, l);
        int o = (t * COUTC + co) * CMIDC + cm;
        g_wl2H[o] = h; g_wl2L[o] = l;
    }
    if (idx < CMIDC * CINC) {
        __nv_bfloat16 h, l; bsplit(wl1[idx], h, l);
        g_w1H[idx] = h; g_w1L[idx] = l;   // already [cm][ci]
    }
}

// ---------------------------------------------------------------------------
// K3: bottleneck GEMM via HMMA, 3-term split w/ register-fragment reuse.
//     mid = x @ w1^T + b_low1.  M=16384, N=64, K=256 (4 chunks of 64).
//     CTA 128px x 64cm, 8 warps of 32x32.
// ---------------------------------------------------------------------------
#define MD_BIAS 0
#define MD_AH   1024
#define MD_AL   (MD_AH + 2*16384)
#define MD_BH   (MD_AL + 2*16384)
#define MD_BL   (MD_BH + 2*8192)
#define MD_SMEM (MD_BL + 2*8192)      // 99328

__global__ __launch_bounds__(256, 2)
void k_mid(const float* __restrict__ b_low1) {
    extern __shared__ char sm[];
    int tid = threadIdx.x;
    int m0  = blockIdx.x * 128;
    uint32_t sb = smem_u32(sm);
    float* sbias = (float*)(sm + MD_BIAS);
    if (tid < 64) sbias[tid] = b_low1[tid];

    int wid = tid >> 5, lane = tid & 31;
    int wm = wid & 3, wn = wid >> 2;
    float acc[2][4][4];
#pragma unroll
    for (int i = 0; i < 2; i++)
#pragma unroll
        for (int j = 0; j < 4; j++)
#pragma unroll
            for (int k = 0; k < 4; k++) acc[i][j][k] = 0.f;

    int arow = tid >> 1, aj0 = (tid & 1) * 4;   // 4 cpa16/tile
    int brow = tid >> 2, bj0 = (tid & 3) * 2;   // 2 cpa16/tile

    auto stage = [&](int c, int buf) {
        int koff = c * 64;
        const char* aH = (const char*)(g_xH + (size_t)(m0 + arow) * CINC + koff);
        const char* aL = (const char*)(g_xL + (size_t)(m0 + arow) * CINC + koff);
        uint32_t dAH = sb + MD_AH + buf * 16384 + arow * 128;
        uint32_t dAL = sb + MD_AL + buf * 16384 + arow * 128;
#pragma unroll
        for (int i = 0; i < 4; i++) {
            int j16 = aj0 + i;
            uint32_t sw = (uint32_t)((j16 ^ (arow & 7)) * 16);
            cpa16(dAH + sw, aH + j16 * 16, 16);
            cpa16(dAL + sw, aL + j16 * 16, 16);
        }
        const char* bH = (const char*)(g_w1H + (size_t)brow * CINC + koff);
        const char* bL = (const char*)(g_w1L + (size_t)brow * CINC + koff);
        uint32_t dBH = sb + MD_BH + buf * 8192 + brow * 128;
        uint32_t dBL = sb + MD_BL + buf * 8192 + brow * 128;
#pragma unroll
        for (int i = 0; i < 2; i++) {
            int j16 = bj0 + i;
            uint32_t sw = (uint32_t)((j16 ^ (brow & 7)) * 16);
            cpa16(dBH + sw, bH + j16 * 16, 16);
            cpa16(dBL + sw, bL + j16 * 16, 16);
        }
        cpa_commit();
    };

    stage(0, 0);
    const int nCh = 4;
    for (int c = 0; c < nCh; c++) {
        int buf = c & 1;
        if (c + 1 < nCh) {
            stage(c + 1, buf ^ 1);
            asm volatile("cp.async.wait_group 1;" ::: "memory");
        } else {
            asm volatile("cp.async.wait_group 0;" ::: "memory");
        }
        __syncthreads();
        uint32_t aBH = sb + MD_AH + buf * 16384;
        uint32_t aBL = sb + MD_AL + buf * 16384;
        uint32_t bBH = sb + MD_BH + buf * 8192;
        uint32_t bBL = sb + MD_BL + buf * 8192;
#pragma unroll
        for (int ks = 0; ks < 4; ks++) {
            uint32_t aH[2][4], aL[2][4], btH[4][2], btL[4][2];
#pragma unroll
            for (int mi = 0; mi < 2; mi++) {
                int row = wm * 32 + mi * 16 + (lane & 15);
                int j16 = ks * 2 + (lane >> 4);
                uint32_t sw = row * 128 + ((j16 ^ (row & 7)) * 16);
                ldsm4(aH[mi][0], aH[mi][1], aH[mi][2], aH[mi][3], aBH + sw);
                ldsm4(aL[mi][0], aL[mi][1], aL[mi][2], aL[mi][3], aBL + sw);
            }
#pragma unroll
            for (int g = 0; g < 2; g++) {
                int row = wn * 32 + g * 16 + (lane & 15);
                int j16 = ks * 2 + (lane >> 4);
                uint32_t sw = row * 128 + ((j16 ^ (row & 7)) * 16);
                uint32_t r0, r1, r2, r3;
                ldsm4(r0, r1, r2, r3, bBH + sw);
                btH[2 * g][0] = r0;     btH[2 * g][1] = r2;
                btH[2 * g + 1][0] = r1; btH[2 * g + 1][1] = r3;
                ldsm4(r0, r1, r2, r3, bBL + sw);
                btL[2 * g][0] = r0;     btL[2 * g][1] = r2;
                btL[2 * g + 1][0] = r1; btL[2 * g + 1][1] = r3;
            }
#pragma unroll
            for (int mi = 0; mi < 2; mi++)
#pragma unroll
                for (int ni = 0; ni < 4; ni++) {
                    mma_bf16(acc[mi][ni], aH[mi], btH[ni]);
                    mma_bf16(acc[mi][ni], aH[mi], btL[ni]);
                    mma_bf16(acc[mi][ni], aL[mi], btH[ni]);
                }
        }
        __syncthreads();
    }

    // epilogue: + bias, split to g_mH/g_mL
#pragma unroll
    for (int mi = 0; mi < 2; mi++)
#pragma unroll
        for (int hb = 0; hb < 2; hb++) {
            int rloc = wm * 32 + mi * 16 + hb * 8 + (lane >> 2);
            int pix = m0 + rloc;
#pragma unroll
            for (int ni = 0; ni < 4; ni++) {
#pragma unroll
                for (int e = 0; e < 2; e++) {
                    int cm = wn * 32 + ni * 8 + (lane & 3) * 2 + e;
                    float v = acc[mi][ni][hb * 2 + e] + sbias[cm];
                    __nv_bfloat16 h, l; bsplit(v, h, l);
                    g_mH[(size_t)pix * CMIDC + cm] = h;
                    g_mL[(size_t)pix * CMIDC + cm] = l;
                }
            }
        }
}

// ---------------------------------------------------------------------------
// K4: per-phase mask compaction
// ---------------------------------------------------------------------------
__global__ void k_compact(const float* __restrict__ mask) {
    int phase = blockIdx.y, py = phase >> 1, px = phase & 1;
    int tid = threadIdx.x;
    int pid = blockIdx.x * 256 + tid;
    int b = pid >> 12, h = (pid >> 6) & 63, w = pid & 63;
    float mv = mask[(b * HOUT + 2 * h + py) * WOUT + 2 * w + px];
    bool hi = mv > 0.5f;

    __shared__ int cHi[8], oHi[8], oLo[8];
    __shared__ int bHi, bLo;
    int lane = tid & 31, wd = tid >> 5;
    unsigned bal = __ballot_sync(0xffffffffu, hi);
    if (lane == 0) cHi[wd] = __popc(bal);
    __syncthreads();
    if (tid == 0) {
        int sh = 0, sl = 0;
        for (int i = 0; i < 8; i++) {
            oHi[i] = sh; sh += cHi[i];
            oLo[i] = sl; sl += 32 - cHi[i];
        }
        bHi = atomicAdd(&g_cnt[phase], sh);
        bLo = atomicAdd(&g_cnt[4 + phase], sl);
    }
    __syncthreads();
    unsigned lt = (1u << lane) - 1u;
    if (hi) g_list[phase][bHi + oHi[wd] + __popc(bal & lt)] = pid;
    else    g_list[4 + phase][bLo + oLo[wd] + __popc((~bal) & lt)] = pid;
}

// ---------------------------------------------------------------------------
// K5: main list-gathered implicit GEMM, HMMA bf16, 3-term split with
//     register-fragment reuse. CTA = 128 px x 256 co (full co, A staged once).
//     512 threads, 16 warps of 32px x 64co. K chunks of 64 (Kin), double buf.
// ---------------------------------------------------------------------------
#define KM_SID  0
#define KM_BIAS 1024
#define KM_AH   2048
#define KM_AL   (KM_AH + 2*16384)
#define KM_BH   (KM_AL + 2*16384)
#define KM_BL   (KM_BH + 2*32768)
#define KM_SMEM (KM_BL + 2*32768)     // 198656

__global__ __launch_bounds__(512, 1)
void k_main(const float* __restrict__ b_high, const float* __restrict__ b_low2,
            float* __restrict__ out) {
    extern __shared__ char sm[];
    int seg   = blockIdx.y;
    int count = g_cnt[seg];
    int m0    = blockIdx.x * 128;
    if (m0 >= count) return;

    int branch = seg >> 2, phase = seg & 3;
    int py = phase >> 1, px = phase & 1;
    int Kin  = branch ? CMIDC : CINC;
    int cpt  = Kin >> 6;            // Kin chunks per tap: 4 high / 1 low
    int ntap = (py + 1) * (px + 1);
    int nCh  = ntap * cpt;
    const __nv_bfloat16* AH = branch ? g_mH : g_xH;
    const __nv_bfloat16* AL = branch ? g_mL : g_xL;
    const __nv_bfloat16* WH = branch ? g_wl2H : g_whH;
    const __nv_bfloat16* WL = branch ? g_wl2L : g_whL;
    const float* bias = branch ? b_low2 : b_high;

    int* sid = (int*)(sm + KM_SID);
    float* sbias = (float*)(sm + KM_BIAS);
    int tid = threadIdx.x;
    if (tid < 128) {
        int m = m0 + tid;
        sid[tid] = g_list[seg][m < count ? m : count - 1];
    }
    if (tid < 256) sbias[tid] = bias[tid];
    __syncthreads();
    uint32_t sb = smem_u32(sm);

    int wid = tid >> 5, lane = tid & 31;
    int wm = wid & 3, wn = wid >> 2;    // wm: 32px group, wn: 64co group
    float acc[2][8][4];
#pragma unroll
    for (int i = 0; i < 2; i++)
#pragma unroll
        for (int j = 0; j < 8; j++)
#pragma unroll
            for (int k = 0; k < 4; k++) acc[i][j][k] = 0.f;

    int arow = tid >> 2, aj0 = (tid & 3) * 2;   // 2 cpa16/A tile
    int brow = tid >> 1, bj0 = (tid & 1) * 4;   // 4 cpa16/B tile

    auto stage = [&](int c, int buf) {
        int tap  = c / cpt;
        int koff = (c - tap * cpt) << 6;
        int dh = c_dh[phase][tap], dw = c_dw[phase][tap], kx = c_kx[phase][tap];
        int id = sid[arow];
        int b = id >> 12, h = (id >> 6) & 63, w = id & 63;
        int hh = h + dh, ww = w + dw;
        bool ok = (hh < HH) && (ww < WWD);
        size_t abase = (size_t)((((b << 6) + (ok ? hh : h)) << 6) + (ok ? ww : w))
                       * Kin + koff;
        const char* aH = (const char*)(AH + abase);
        const char* aL = (const char*)(AL + abase);
        uint32_t dAH = sb + KM_AH + buf * 16384 + arow * 128;
        uint32_t dAL = sb + KM_AL + buf * 16384 + arow * 128;
        int asz = ok ? 16 : 0;
#pragma unroll
        for (int i = 0; i < 2; i++) {
            int j16 = aj0 + i;
            uint32_t sw = (uint32_t)((j16 ^ (arow & 7)) * 16);
            cpa16(dAH + sw, aH + j16 * 16, asz);
            cpa16(dAL + sw, aL + j16 * 16, asz);
        }
        size_t bbase = (size_t)(kx * COUTC + brow) * Kin + koff;
        const char* bH = (const char*)(WH + bbase);
        const char* bL = (const char*)(WL + bbase);
        uint32_t dBH = sb + KM_BH + buf * 32768 + brow * 128;
        uint32_t dBL = sb + KM_BL + buf * 32768 + brow * 128;
#pragma unroll
        for (int i = 0; i < 4; i++) {
            int j16 = bj0 + i;
            uint32_t sw = (uint32_t)((j16 ^ (brow & 7)) * 16);
            cpa16(dBH + sw, bH + j16 * 16, 16);
            cpa16(dBL + sw, bL + j16 * 16, 16);
        }
        cpa_commit();
    };

    stage(0, 0);
    for (int c = 0; c < nCh; c++) {
        int buf = c & 1;
        if (c + 1 < nCh) {
            stage(c + 1, buf ^ 1);
            asm volatile("cp.async.wait_group 1;" ::: "memory");
        } else {
            asm volatile("cp.async.wait_group 0;" ::: "memory");
        }
        __syncthreads();
        uint32_t aBH = sb + KM_AH + buf * 16384;
        uint32_t aBL = sb + KM_AL + buf * 16384;
        uint32_t bBH = sb + KM_BH + buf * 32768;
        uint32_t bBL = sb + KM_BL + buf * 32768;
#pragma unroll
        for (int ks = 0; ks < 4; ks++) {
            uint32_t aH[2][4], aL[2][4], btH[8][2], btL[8][2];
#pragma unroll
            for (int mi = 0; mi < 2; mi++) {
                int row = wm * 32 + mi * 16 + (lane & 15);
                int j16 = ks * 2 + (lane >> 4);
                uint32_t sw = row * 128 + ((j16 ^ (row & 7)) * 16);
                ldsm4(aH[mi][0], aH[mi][1], aH[mi][2], aH[mi][3], aBH + sw);
                ldsm4(aL[mi][0], aL[mi][1], aL[mi][2], aL[mi][3], aBL + sw);
            }
#pragma unroll
            for (int g = 0; g < 4; g++) {
                int row = wn * 64 + g * 16 + (lane & 15);
                int j16 = ks * 2 + (lane >> 4);
                uint32_t sw = row * 128 + ((j16 ^ (row & 7)) * 16);
                uint32_t r0, r1, r2, r3;
                ldsm4(r0, r1, r2, r3, bBH + sw);
                btH[2 * g][0] = r0;     btH[2 * g][1] = r2;
                btH[2 * g + 1][0] = r1; btH[2 * g + 1][1] = r3;
                ldsm4(r0, r1, r2, r3, bBL + sw);
                btL[2 * g][0] = r0;     btL[2 * g][1] = r2;
                btL[2 * g + 1][0] = r1; btL[2 * g + 1][1] = r3;
            }
#pragma unroll
            for (int mi = 0; mi < 2; mi++)
#pragma unroll
                for (int ni = 0; ni < 8; ni++) {
                    mma_bf16(acc[mi][ni], aH[mi], btH[ni]);
                    mma_bf16(acc[mi][ni], aH[mi], btL[ni]);
                    mma_bf16(acc[mi][ni], aL[mi], btH[ni]);
                }
        }
        __syncthreads();
    }

    // epilogue: + bias, scatter to NCHW
#pragma unroll
    for (int mi = 0; mi < 2; mi++)
#pragma unroll
        for (int hb = 0; hb < 2; hb++) {
            int rloc = wm * 32 + mi * 16 + hb * 8 + (lane >> 2);
            if (m0 + rloc >= count) continue;
            int id = sid[rloc];
            int b = id >> 12, h = (id >> 6) & 63, w = id & 63;
            int ho = 2 * h + py, wo = 2 * w + px;
            float* op = out + (((size_t)b * COUTC) * HOUT + ho) * WOUT + wo;
#pragma unroll
            for (int ni = 0; ni < 8; ni++) {
                int n0 = wn * 64 + ni * 8 + (lane & 3) * 2;
                op[(size_t)n0 * (HOUT * WOUT)] =
                    acc[mi][ni][hb * 2 + 0] + sbias[n0];
                op[(size_t)(n0 + 1) * (HOUT * WOUT)] =
                    acc[mi][ni][hb * 2 + 1] + sbias[n0 + 1];
            }
        }
}

// ---------------------------------------------------------------------------
// launch
// Inputs (metadata order): inx, mask, inv_mask, w_high, b_high,
//                          w_low1, b_low1, w_low2, b_low2
// ---------------------------------------------------------------------------
extern "C" void kernel_launch(void* const* d_in, const int* in_sizes, int n_in,
                              void* d_out, int out_size) {
    const float* inx    = (const float*)d_in[0];
    const float* mask   = (const float*)d_in[1];
    const float* w_high = (const float*)d_in[3];
    const float* b_high = (const float*)d_in[4];
    const float* w_low1 = (const float*)d_in[5];
    const float* b_low1 = (const float*)d_in[6];
    const float* w_low2 = (const float*)d_in[7];
    const float* b_low2 = (const float*)d_in[8];
    float* out = (float*)d_out;

    cudaFuncSetAttribute(k_mid,  cudaFuncAttributeMaxDynamicSharedMemorySize,
                         MD_SMEM);
    cudaFuncSetAttribute(k_main, cudaFuncAttributeMaxDynamicSharedMemorySize,
                         KM_SMEM);

    k_zero<<<1, 32>>>();
    k_tin<<<dim3(128, 8, BB), dim3(32, 8)>>>(inx);
    k_tw<<<(9 * CINC * COUTC + 255) / 256, 256>>>(w_high, w_low2, w_low1);
    k_mid<<<NPIX / 128, 256, MD_SMEM>>>(b_low1);
    k_compact<<<dim3(NPIX / 256, 4), 256>>>(mask);
    k_main<<<dim3(NPIX / 128, 8), 512, KM_SMEM>>>(b_high, b_low2, out);
}